// round 6
// baseline (speedup 1.0000x reference)
#include <cuda_runtime.h>
#include <cstdint>

// Problem dims
#define Sn 1024
#define Bn 64
#define Dn 256
#define Hn 256
#define G4 1024               // 4*H gate columns
#define BH (Bn*Hn)            // 16384
#define GB 16                 // batch groups (4 batches each)
#define GJ 8                  // j groups (32 hidden units each) == cluster size
#define NBLK (GB*GJ)          // 128 blocks

// ---------------- scratch (static device allocations only) ----------------
__device__ float g_P[(size_t)Sn * G4 * Bn];     // [t][ig][jg][g][jl][bl] (256 MB)
__device__ float g_ysT[(size_t)Sn * Hn * Bn];   // h history [t][j][b] (64 MB)
__device__ float g_Wxr[G4 * Dn];                // [c][k] x-part weights (c=g*256+j)
__device__ float g_Wh2[GJ * Hn * 128];          // [jg][kc][kl][cg][cp][e] reg-GEMM layout
__device__ float g_thb[G4];                     // b + theta folded
__device__ float g_cT[Hn * Bn];                 // final cell state [j][b]

// ---------------- prep ----------------
__global__ void prep_kernel(const float* Wf, const float* bf,
                            const float* Wi, const float* bi,
                            const float* Wu, const float* bu,
                            const float* Wo, const float* bo,
                            const float* thf, const float* thi,
                            const float* thu, const float* tho) {
    int idx = blockIdx.x * blockDim.x + threadIdx.x;
    const float* W[4]  = {Wf, Wi, Wu, Wo};
    const float* bb[4] = {bf, bi, bu, bo};
    const float* th[4] = {thf, thi, thu, tho};
    if (idx < G4 * Dn) {                        // Wxr[c][k] = W_g[j][k], c=g*256+j
        int c = idx >> 8, k = idx & 255;
        int g = c >> 8, j = c & 255;
        g_Wxr[idx] = W[g][j * 512 + k];
    }
    if (idx < GJ * Hn * 128) {
        // f = (((jg*8+kc)*32+kl)*32+cg)*4 + cp*2 + e
        int e  = idx & 1;
        int cp = (idx >> 1) & 1;
        int cg = (idx >> 2) & 31;
        int kl = (idx >> 7) & 31;
        int kc = (idx >> 12) & 7;
        int jg = idx >> 15;
        int j = jg * 32 + cg;
        int k = kc * 32 + kl;
        int g = cp * 2 + e;
        g_Wh2[idx] = W[g][j * 512 + 256 + k];
    }
    if (idx < G4) {
        int g = idx >> 8, j = idx & 255;
        g_thb[idx] = bb[g][j] + th[g][j];
    }
}

// ---------------- phase 1: X projection SGEMM (65536 x 1024 x 256) ----------------
__global__ void __launch_bounds__(256) xproj_kernel(const float* __restrict__ X) {
    __shared__ float As[16][128];
    __shared__ float Bs[16][128];
    int tid = threadIdx.x;
    int n0 = blockIdx.x * 128;
    int m0 = blockIdx.y * 128;
    int tx = tid & 15, ty = tid >> 4;
    float acc[8][8];
#pragma unroll
    for (int i = 0; i < 8; i++)
#pragma unroll
        for (int j = 0; j < 8; j++) acc[i][j] = 0.0f;

    for (int k0 = 0; k0 < 256; k0 += 16) {
#pragma unroll
        for (int i = 0; i < 2; i++) {
            int fidx = tid + i * 256;
            int r = fidx >> 2, kq = (fidx & 3) * 4;
            float4 va = *(const float4*)&X[(size_t)(m0 + r) * 256 + k0 + kq];
            As[kq + 0][r] = va.x; As[kq + 1][r] = va.y;
            As[kq + 2][r] = va.z; As[kq + 3][r] = va.w;
            float4 vb = *(const float4*)&g_Wxr[(size_t)(n0 + r) * 256 + k0 + kq];
            Bs[kq + 0][r] = vb.x; Bs[kq + 1][r] = vb.y;
            Bs[kq + 2][r] = vb.z; Bs[kq + 3][r] = vb.w;
        }
        __syncthreads();
#pragma unroll
        for (int kk = 0; kk < 16; kk++) {
            float a[8], b[8];
#pragma unroll
            for (int i = 0; i < 8; i++) a[i] = As[kk][ty * 8 + i];
#pragma unroll
            for (int j = 0; j < 8; j++) b[j] = Bs[kk][tx * 8 + j];
#pragma unroll
            for (int i = 0; i < 8; i++)
#pragma unroll
                for (int j = 0; j < 8; j++) acc[i][j] += a[i] * b[j];
        }
        __syncthreads();
    }
    // epilogue: bl 0..3 = acc rows (i&3) -> coalesced STG.128
    int tcur = blockIdx.y * 2 + (ty >> 3);
    int g = n0 >> 8;                       // constant per block (n0 128-aligned)
#pragma unroll
    for (int ih = 0; ih < 2; ih++) {
        int ig = (ty & 7) * 2 + ih;
#pragma unroll
        for (int j = 0; j < 8; j++) {
            int c = n0 + tx * 8 + j;
            int jj = c & 255;
            int jg = jj >> 5, jl = jj & 31;
            float tb = g_thb[c];
            float4 v = make_float4(acc[ih * 4 + 0][j] + tb, acc[ih * 4 + 1][j] + tb,
                                   acc[ih * 4 + 2][j] + tb, acc[ih * 4 + 3][j] + tb);
            size_t base = ((((size_t)tcur * GB + ig) * GJ + jg) << 9) + g * 128 + jl * 4;
            *(float4*)&g_P[base] = v;
        }
    }
}

// ---------------- phase 2: clustered persistent LSTM recurrence ----------------
// 128 blocks = 16 clusters of 8. Rank jg owns 32 hidden units. Weights in regs.
// smem floats: [0..3] mbar | shH[2][256][4] | shRed u64[8][324] | shP[2][512]
#define SHH_OFF   4
#define SHRED_OFF (SHH_OFF + 2048)
#define SHP_OFF   (SHRED_OFF + 8 * 324 * 2)
#define SMEM_MAIN_FLOATS (SHP_OFF + 1024)
#define SMEM_MAIN_BYTES  (SMEM_MAIN_FLOATS * 4)

__device__ __forceinline__ float fast_sig_cos(float x) {
    float c = __cosf(x);
    return __fdividef(1.0f, 1.0f + __expf(-c));
}
__device__ __forceinline__ float fast_tanh(float x) {
    return 1.0f - __fdividef(2.0f, __expf(2.0f * x) + 1.0f);
}

__global__ void __launch_bounds__(256, 1) __cluster_dims__(GJ, 1, 1)
lstm_main_kernel() {
    extern __shared__ float sm[];
    int tid = threadIdx.x;
    uint32_t jg;
    asm("mov.u32 %0, %%cluster_ctarank;" : "=r"(jg));
    int ig = blockIdx.x >> 3;

    uint32_t sbase;
    asm("{ .reg .u64 t0; cvta.to.shared.u64 t0, %1; cvt.u32.u64 %0, t0; }"
        : "=r"(sbase) : "l"(sm));
    const uint32_t mb_a  = sbase;                   // mbarrier (8B)
    const uint32_t shH_a = sbase + SHH_OFF * 4;
    const uint32_t shR_a = sbase + SHRED_OFF * 4;
    const uint32_t shP_a = sbase + SHP_OFF * 4;
    float* shP = sm + SHP_OFF;

    const int kc = tid >> 5;          // k chunk (0..7, 32 k each)
    const int cg = tid & 31;          // unit-local jl this thread computes
    const int bl = tid & 3;           // finalize: batch-local
    const int jl = tid >> 2;          // finalize: unit-local (tid<128)

    // kick off cp.async for P[0] (warps 4-7) as early as possible
    if (tid >= 128) {
        int li = tid - 128;
        size_t src = ((((size_t)0 * GB + ig) * GJ + jg) << 9) + li * 4;
        uint32_t dst = shP_a + li * 16;
        asm volatile("cp.async.ca.shared.global [%0], [%1], 16;"
                     :: "r"(dst), "l"(g_P + src));
        asm volatile("cp.async.commit_group;");
    }

    // preload weights into registers: 64 u64 = 128 floats
    unsigned long long w0[32], w1[32];
    {
        const ulonglong2* ws = (const ulonglong2*)(g_Wh2 + (((size_t)jg * 8 + kc) << 12));
#pragma unroll
        for (int kl = 0; kl < 32; kl++) {
            ulonglong2 v = ws[kl * 32 + cg];
            w0[kl] = v.x; w1[kl] = v.y;
        }
    }
    // precompute remote bases (mapa hoisted out of the loop)
    uint32_t rbH[GJ];
#pragma unroll
    for (int r = 0; r < GJ; r++) {
        asm("mapa.shared::cluster.u32 %0, %1, %2;" : "=r"(rbH[r]) : "r"(shH_a), "r"(r));
    }
    uint32_t rb_mb = 0;
    if (tid < GJ) {
        asm("mapa.shared::cluster.u32 %0, %1, %2;" : "=r"(rb_mb) : "r"(mb_a), "r"(tid));
    }
    if (tid == 0) {
        asm volatile("mbarrier.init.shared.b64 [%0], %1;" :: "r"(mb_a), "r"(GJ));
    }
    __syncthreads();
    asm volatile("barrier.cluster.arrive.aligned;" ::: "memory");
    asm volatile("barrier.cluster.wait.aligned;" ::: "memory");

    float cell = 0.0f;

    for (int t = 0; t < Sn; t++) {
        // warps 4-7: issue cp.async for P[t+1] into buf[(t+1)&1]
        if (tid >= 128) {
            int li = tid - 128;
            int tn = (t + 1 < Sn) ? t + 1 : Sn - 1;
            size_t src = ((((size_t)tn * GB + ig) * GJ + jg) << 9) + li * 4;
            uint32_t dst = shP_a + ((t + 1) & 1) * 2048 + li * 16;
            asm volatile("cp.async.ca.shared.global [%0], [%1], 16;"
                         :: "r"(dst), "l"(g_P + src));
            asm volatile("cp.async.commit_group;");
        }
        if (t > 0) {
            // single-thread wait, CLUSTER-scope acquire (sound: pairs with the
            // remote ranks' arrive.release.cluster); bar.sync broadcasts the
            // synchronization to the rest of the CTA.
            if (tid == 0) {
                uint32_t ph = (t - 1) & 1;
                asm volatile(
                    "{\n\t.reg .pred P;\n"
                    "WL_%=:\n\t"
                    "mbarrier.try_wait.parity.acquire.cluster.shared::cta.b64 P, [%0], %1, 0x989680;\n\t"
                    "@!P bra WL_%=;\n\t}"
                    :: "r"(mb_a), "r"(ph) : "memory");
            }
            __syncthreads();            // syncA: h[t-1] visible to all
            // compute: thread (kc,cg) -> 4 gate cols (unit cg) x 4 batches over 32 k
            uint32_t ha = shH_a + ((t - 1) & 1) * 4096 + kc * 512;
            unsigned long long a00 = 0, a01 = 0, a02 = 0, a03 = 0;  // (f,i) x b
            unsigned long long a10 = 0, a11 = 0, a12 = 0, a13 = 0;  // (u,o) x b
#pragma unroll
            for (int kl = 0; kl < 32; kl++) {
                float hx, hy, hz, hw;
                asm volatile("ld.shared.v4.f32 {%0,%1,%2,%3}, [%4];"
                             : "=f"(hx), "=f"(hy), "=f"(hz), "=f"(hw) : "r"(ha));
                unsigned long long h0, h1, h2, h3;
                asm("mov.b64 %0, {%1, %1};" : "=l"(h0) : "f"(hx));
                asm("mov.b64 %0, {%1, %1};" : "=l"(h1) : "f"(hy));
                asm("mov.b64 %0, {%1, %1};" : "=l"(h2) : "f"(hz));
                asm("mov.b64 %0, {%1, %1};" : "=l"(h3) : "f"(hw));
                asm("fma.rn.f32x2 %0, %1, %2, %0;" : "+l"(a00) : "l"(w0[kl]), "l"(h0));
                asm("fma.rn.f32x2 %0, %1, %2, %0;" : "+l"(a01) : "l"(w0[kl]), "l"(h1));
                asm("fma.rn.f32x2 %0, %1, %2, %0;" : "+l"(a02) : "l"(w0[kl]), "l"(h2));
                asm("fma.rn.f32x2 %0, %1, %2, %0;" : "+l"(a03) : "l"(w0[kl]), "l"(h3));
                asm("fma.rn.f32x2 %0, %1, %2, %0;" : "+l"(a10) : "l"(w1[kl]), "l"(h0));
                asm("fma.rn.f32x2 %0, %1, %2, %0;" : "+l"(a11) : "l"(w1[kl]), "l"(h1));
                asm("fma.rn.f32x2 %0, %1, %2, %0;" : "+l"(a12) : "l"(w1[kl]), "l"(h2));
                asm("fma.rn.f32x2 %0, %1, %2, %0;" : "+l"(a13) : "l"(w1[kl]), "l"(h3));
                ha += 16;
            }
            {
                uint32_t r0 = shR_a + (kc * 324 + (cg * 2) * 5) * 8;
                asm volatile("st.shared.b64 [%0], %1;" :: "r"(r0),      "l"(a00));
                asm volatile("st.shared.b64 [%0], %1;" :: "r"(r0 + 8),  "l"(a01));
                asm volatile("st.shared.b64 [%0], %1;" :: "r"(r0 + 16), "l"(a02));
                asm volatile("st.shared.b64 [%0], %1;" :: "r"(r0 + 24), "l"(a03));
                uint32_t r1 = r0 + 40;
                asm volatile("st.shared.b64 [%0], %1;" :: "r"(r1),      "l"(a10));
                asm volatile("st.shared.b64 [%0], %1;" :: "r"(r1 + 8),  "l"(a11));
                asm volatile("st.shared.b64 [%0], %1;" :: "r"(r1 + 16), "l"(a12));
                asm volatile("st.shared.b64 [%0], %1;" :: "r"(r1 + 24), "l"(a13));
            }
        }
        if (tid >= 128) {
            asm volatile("cp.async.wait_group 1;");   // P[t] landed in buf[t&1]
        }
        __syncthreads();                // syncB: shRed + shP ready
        // finalize: thread (jl, bl) owns unit j = jg*32+jl, batch b = ig*4+bl
        float hval = 0.0f;
        if (tid < 128) {
            const float* pp = shP + (t & 1) * 512 + jl * 4 + bl;
            float s0 = pp[0], s1 = pp[128], s2 = pp[256], s3 = pp[384];
            if (t > 0) {
                unsigned long long sfi = 0, suo = 0;
                uint32_t rfi = shR_a + ((jl * 2) * 5 + bl) * 8;
                uint32_t ruo = rfi + 40;
#pragma unroll
                for (int k2 = 0; k2 < 8; k2++) {
                    unsigned long long vfi, vuo;
                    asm volatile("ld.shared.b64 %0, [%1];" : "=l"(vfi) : "r"(rfi));
                    asm volatile("ld.shared.b64 %0, [%1];" : "=l"(vuo) : "r"(ruo));
                    asm("add.rn.f32x2 %0, %0, %1;" : "+l"(sfi) : "l"(vfi));
                    asm("add.rn.f32x2 %0, %0, %1;" : "+l"(suo) : "l"(vuo));
                    rfi += 324 * 8; ruo += 324 * 8;
                }
                float vf, vi, vu, vo;
                asm("mov.b64 {%0, %1}, %2;" : "=f"(vf), "=f"(vi) : "l"(sfi));
                asm("mov.b64 {%0, %1}, %2;" : "=f"(vu), "=f"(vo) : "l"(suo));
                s0 += vf; s1 += vi; s2 += vu; s3 += vo;
            }
            float f  = fast_sig_cos(s0);
            float ii = fast_sig_cos(s1);
            float u  = fast_tanh(__cosf(s2));
            float o  = fast_sig_cos(s3);
            cell = f * cell + ii * u;
            hval = o * fast_tanh(cell);
            g_ysT[(size_t)t * BH + (size_t)(jg * 32 + jl) * 64 + ig * 4 + bl] = hval;
            // publish h[t] to all ranks: packer (bl==0) stores float4 per unit
            float h1 = __shfl_down_sync(0xffffffffu, hval, 1);
            float h2 = __shfl_down_sync(0xffffffffu, hval, 2);
            float h3 = __shfl_down_sync(0xffffffffu, hval, 3);
            if (bl == 0 && t + 1 < Sn) {
                uint32_t loff = (t & 1) * 4096 + (jg * 32 + jl) * 16;
                uint32_t u0 = __float_as_uint(hval), u1 = __float_as_uint(h1);
                uint32_t u2 = __float_as_uint(h2),   u3 = __float_as_uint(h3);
#pragma unroll
                for (int r = 0; r < GJ; r++) {
                    asm volatile("st.shared::cluster.v4.b32 [%0], {%1,%2,%3,%4};"
                                 :: "r"(rbH[r] + loff), "r"(u0), "r"(u1), "r"(u2), "r"(u3));
                }
            }
        }
        __syncthreads();                // syncC: publishes issued by all
        if (tid < GJ && t + 1 < Sn) {
            asm volatile("mbarrier.arrive.release.cluster.shared::cluster.b64 _, [%0];"
                         :: "r"(rb_mb) : "memory");
        }
    }
    if (tid < 128) g_cT[(size_t)(jg * 32 + jl) * 64 + ig * 4 + bl] = cell;
}

// ---------------- phase 3a: qfeat = cos(ysT + phi), transpose to [B][S][H] ----------------
__global__ void __launch_bounds__(256) qfeat_kernel(const float* __restrict__ phi,
                                                    float* __restrict__ out) {
    __shared__ float smq[64 * 129];
    int s = blockIdx.x, half = blockIdx.y;
    int h0 = half * 128;
    int tid = threadIdx.x;
    const float* src = g_ysT + (size_t)s * BH + (size_t)h0 * 64;
#pragma unroll
    for (int r = 0; r < 32; r++) {
        int i = tid + r * 256;
        int h = i >> 6, b = i & 63;
        smq[b * 129 + h] = __cosf(src[i] + phi[h0 + h]);
    }
    __syncthreads();
#pragma unroll
    for (int r = 0; r < 32; r++) {
        int i = tid + r * 256;
        int b = i >> 7, h = i & 127;
        out[(size_t)b * (Sn * Hn) + (size_t)s * Hn + h0 + h] = smq[b * 129 + h];
    }
}

// ---------------- phase 3b: attention context + residual add ----------------
__global__ void __launch_bounds__(128) attn_kernel(const float* __restrict__ tha,
                                                   float* __restrict__ out) {
    int b = blockIdx.x;
    int h = blockIdx.y * 128 + threadIdx.x;
    float th = tha[h];
    float se = 0.0f, sq = 0.0f;
    size_t base = (size_t)b * Sn * Hn + h;
#pragma unroll 4
    for (int s = 0; s < Sn; s++) {
        float q = out[base + (size_t)s * Hn];
        float e = __expf(fast_tanh(__cosf(q + th)));
        se += e; sq += e * q;
    }
    float ctx = sq / se;
#pragma unroll 4
    for (int s = 0; s < Sn; s++) {
        out[base + (size_t)s * Hn] += ctx;
    }
}

// ---------------- phase 3c: hx, cx tail ----------------
__global__ void tail_kernel(float* __restrict__ out) {
    int i = blockIdx.x * blockDim.x + threadIdx.x;
    if (i < BH) {
        int b = i >> 8, jx = i & 255;
        out[(size_t)Bn * Sn * Hn + i]      = g_ysT[(size_t)(Sn - 1) * BH + jx * 64 + b];
        out[(size_t)Bn * Sn * Hn + BH + i] = g_cT[jx * 64 + b];
    }
}

// ---------------- launch ----------------
extern "C" void kernel_launch(void* const* d_in, const int* in_sizes, int n_in,
                              void* d_out, int out_size) {
    const float* X   = (const float*)d_in[0];
    const float* Wf  = (const float*)d_in[1];
    const float* bf  = (const float*)d_in[2];
    const float* Wi  = (const float*)d_in[3];
    const float* bi  = (const float*)d_in[4];
    const float* Wu  = (const float*)d_in[5];
    const float* bu  = (const float*)d_in[6];
    const float* Wo  = (const float*)d_in[7];
    const float* bo  = (const float*)d_in[8];
    const float* thf = (const float*)d_in[9];
    const float* thi = (const float*)d_in[10];
    const float* thu = (const float*)d_in[11];
    const float* tho = (const float*)d_in[12];
    const float* phi = (const float*)d_in[13];
    const float* tha = (const float*)d_in[14];
    float* out = (float*)d_out;

    cudaFuncSetAttribute(lstm_main_kernel,
                         cudaFuncAttributeMaxDynamicSharedMemorySize, SMEM_MAIN_BYTES);

    prep_kernel<<<1024, 256>>>(Wf, bf, Wi, bi, Wu, bu, Wo, bo, thf, thi, thu, tho);
    xproj_kernel<<<dim3(8, 512), 256>>>(X);
    lstm_main_kernel<<<NBLK, 256, SMEM_MAIN_BYTES>>>();
    qfeat_kernel<<<dim3(Sn, 2), 256>>>(phi, out);
    attn_kernel<<<dim3(Bn, 2), 128>>>(tha, out);
    if (out_size >= Bn * Sn * Hn + 2 * BH) {
        tail_kernel<<<64, 256>>>(out);
    }
}

// round 7
// speedup vs baseline: 1.0008x; 1.0008x over previous
#include <cuda_runtime.h>
#include <cstdint>

// Problem dims
#define Sn 1024
#define Bn 64
#define Dn 256
#define Hn 256
#define G4 1024               // 4*H gate columns
#define BH (Bn*Hn)            // 16384
#define GB 16                 // batch groups (4 batches each)
#define GJ 8                  // j groups (32 hidden units each) == cluster size
#define NBLK (GB*GJ)          // 128 blocks

// ---------------- scratch (static device allocations only) ----------------
__device__ float g_P[(size_t)Sn * G4 * Bn];     // [t][ig][jg][g][jl][bl] (256 MB)
__device__ float g_ysT[(size_t)Sn * Hn * Bn];   // h history [t][j][b] (64 MB)
__device__ float g_Wxr[G4 * Dn];                // [c][k] x-part weights (c=g*256+j)
__device__ float g_Wh2[GJ * Hn * 128];          // [jg][kc][kl][cg][cp][e] reg-GEMM layout
__device__ float g_thb[G4];                     // b + theta folded
__device__ float g_cT[Hn * Bn];                 // final cell state [j][b]

// ---------------- prep ----------------
__global__ void prep_kernel(const float* Wf, const float* bf,
                            const float* Wi, const float* bi,
                            const float* Wu, const float* bu,
                            const float* Wo, const float* bo,
                            const float* thf, const float* thi,
                            const float* thu, const float* tho) {
    int idx = blockIdx.x * blockDim.x + threadIdx.x;
    const float* W[4]  = {Wf, Wi, Wu, Wo};
    const float* bb[4] = {bf, bi, bu, bo};
    const float* th[4] = {thf, thi, thu, tho};
    if (idx < G4 * Dn) {                        // Wxr[c][k] = W_g[j][k], c=g*256+j
        int c = idx >> 8, k = idx & 255;
        int g = c >> 8, j = c & 255;
        g_Wxr[idx] = W[g][j * 512 + k];
    }
    if (idx < GJ * Hn * 128) {
        // f = (((jg*8+kc)*32+kl)*32+cg)*4 + cp*2 + e
        int e  = idx & 1;
        int cp = (idx >> 1) & 1;
        int cg = (idx >> 2) & 31;
        int kl = (idx >> 7) & 31;
        int kc = (idx >> 12) & 7;
        int jg = idx >> 15;
        int j = jg * 32 + cg;
        int k = kc * 32 + kl;
        int g = cp * 2 + e;
        g_Wh2[idx] = W[g][j * 512 + 256 + k];
    }
    if (idx < G4) {
        int g = idx >> 8, j = idx & 255;
        g_thb[idx] = bb[g][j] + th[g][j];
    }
}

// ---------------- phase 1: X projection SGEMM (65536 x 1024 x 256) ----------------
__global__ void __launch_bounds__(256) xproj_kernel(const float* __restrict__ X) {
    __shared__ float As[16][128];
    __shared__ float Bs[16][128];
    int tid = threadIdx.x;
    int n0 = blockIdx.x * 128;
    int m0 = blockIdx.y * 128;
    int tx = tid & 15, ty = tid >> 4;
    float acc[8][8];
#pragma unroll
    for (int i = 0; i < 8; i++)
#pragma unroll
        for (int j = 0; j < 8; j++) acc[i][j] = 0.0f;

    for (int k0 = 0; k0 < 256; k0 += 16) {
#pragma unroll
        for (int i = 0; i < 2; i++) {
            int fidx = tid + i * 256;
            int r = fidx >> 2, kq = (fidx & 3) * 4;
            float4 va = *(const float4*)&X[(size_t)(m0 + r) * 256 + k0 + kq];
            As[kq + 0][r] = va.x; As[kq + 1][r] = va.y;
            As[kq + 2][r] = va.z; As[kq + 3][r] = va.w;
            float4 vb = *(const float4*)&g_Wxr[(size_t)(n0 + r) * 256 + k0 + kq];
            Bs[kq + 0][r] = vb.x; Bs[kq + 1][r] = vb.y;
            Bs[kq + 2][r] = vb.z; Bs[kq + 3][r] = vb.w;
        }
        __syncthreads();
#pragma unroll
        for (int kk = 0; kk < 16; kk++) {
            float a[8], b[8];
#pragma unroll
            for (int i = 0; i < 8; i++) a[i] = As[kk][ty * 8 + i];
#pragma unroll
            for (int j = 0; j < 8; j++) b[j] = Bs[kk][tx * 8 + j];
#pragma unroll
            for (int i = 0; i < 8; i++)
#pragma unroll
                for (int j = 0; j < 8; j++) acc[i][j] += a[i] * b[j];
        }
        __syncthreads();
    }
    // epilogue: bl 0..3 = acc rows (i&3) -> coalesced STG.128
    int tcur = blockIdx.y * 2 + (ty >> 3);
    int g = n0 >> 8;                       // constant per block (n0 128-aligned)
#pragma unroll
    for (int ih = 0; ih < 2; ih++) {
        int ig = (ty & 7) * 2 + ih;
#pragma unroll
        for (int j = 0; j < 8; j++) {
            int c = n0 + tx * 8 + j;
            int jj = c & 255;
            int jg = jj >> 5, jl = jj & 31;
            float tb = g_thb[c];
            float4 v = make_float4(acc[ih * 4 + 0][j] + tb, acc[ih * 4 + 1][j] + tb,
                                   acc[ih * 4 + 2][j] + tb, acc[ih * 4 + 3][j] + tb);
            size_t base = ((((size_t)tcur * GB + ig) * GJ + jg) << 9) + g * 128 + jl * 4;
            *(float4*)&g_P[base] = v;
        }
    }
}

// ---------------- phase 2: clustered persistent LSTM recurrence ----------------
// 128 blocks = 16 clusters of 8. Rank jg owns 32 hidden units. Weights in regs.
// smem floats: [0..3] mbar | shH[2][256][4] | shRed u64[8][324] | shP[2][512]
#define SHH_OFF   4
#define SHRED_OFF (SHH_OFF + 2048)
#define SHP_OFF   (SHRED_OFF + 8 * 324 * 2)
#define SMEM_MAIN_FLOATS (SHP_OFF + 1024)
#define SMEM_MAIN_BYTES  (SMEM_MAIN_FLOATS * 4)

__device__ __forceinline__ float fast_sig_cos(float x) {
    float c = __cosf(x);
    return __fdividef(1.0f, 1.0f + __expf(-c));
}
__device__ __forceinline__ float fast_tanh(float x) {
    return 1.0f - __fdividef(2.0f, __expf(2.0f * x) + 1.0f);
}

__global__ void __launch_bounds__(256, 1) __cluster_dims__(GJ, 1, 1)
lstm_main_kernel() {
    extern __shared__ float sm[];
    int tid = threadIdx.x;
    uint32_t jg;
    asm("mov.u32 %0, %%cluster_ctarank;" : "=r"(jg));
    int ig = blockIdx.x >> 3;

    uint32_t sbase;
    asm("{ .reg .u64 t0; cvta.to.shared.u64 t0, %1; cvt.u32.u64 %0, t0; }"
        : "=r"(sbase) : "l"(sm));
    const uint32_t mb_a  = sbase;                   // mbarrier (8B)
    const uint32_t shH_a = sbase + SHH_OFF * 4;
    const uint32_t shR_a = sbase + SHRED_OFF * 4;
    const uint32_t shP_a = sbase + SHP_OFF * 4;
    float* shP = sm + SHP_OFF;

    const int kc = tid >> 5;          // k chunk (0..7, 32 k each)
    const int cg = tid & 31;          // unit-local jl this thread computes
    const int bl = tid & 3;           // finalize: batch-local
    const int jl = tid >> 2;          // finalize: unit-local (tid<128)

    // kick off cp.async for P[0] (warps 4-7) as early as possible
    if (tid >= 128) {
        int li = tid - 128;
        size_t src = ((((size_t)0 * GB + ig) * GJ + jg) << 9) + li * 4;
        uint32_t dst = shP_a + li * 16;
        asm volatile("cp.async.ca.shared.global [%0], [%1], 16;"
                     :: "r"(dst), "l"(g_P + src));
        asm volatile("cp.async.commit_group;");
    }

    // preload weights into registers: 64 u64 = 128 floats
    unsigned long long w0[32], w1[32];
    {
        const ulonglong2* ws = (const ulonglong2*)(g_Wh2 + (((size_t)jg * 8 + kc) << 12));
#pragma unroll
        for (int kl = 0; kl < 32; kl++) {
            ulonglong2 v = ws[kl * 32 + cg];
            w0[kl] = v.x; w1[kl] = v.y;
        }
    }
    // precompute remote bases (mapa hoisted out of the loop)
    uint32_t rbH[GJ];
#pragma unroll
    for (int r = 0; r < GJ; r++) {
        asm("mapa.shared::cluster.u32 %0, %1, %2;" : "=r"(rbH[r]) : "r"(shH_a), "r"(r));
    }
    uint32_t rb_mb = 0;
    if (tid < GJ) {
        asm("mapa.shared::cluster.u32 %0, %1, %2;" : "=r"(rb_mb) : "r"(mb_a), "r"(tid));
    }
    if (tid == 0) {
        asm volatile("mbarrier.init.shared.b64 [%0], %1;" :: "r"(mb_a), "r"(GJ));
    }
    __syncthreads();
    asm volatile("barrier.cluster.arrive.aligned;" ::: "memory");
    asm volatile("barrier.cluster.wait.aligned;" ::: "memory");

    float cell = 0.0f;

    for (int t = 0; t < Sn; t++) {
        // warps 4-7: issue cp.async for P[t+1] into buf[(t+1)&1]
        if (tid >= 128) {
            int li = tid - 128;
            int tn = (t + 1 < Sn) ? t + 1 : Sn - 1;
            size_t src = ((((size_t)tn * GB + ig) * GJ + jg) << 9) + li * 4;
            uint32_t dst = shP_a + ((t + 1) & 1) * 2048 + li * 16;
            asm volatile("cp.async.ca.shared.global [%0], [%1], 16;"
                         :: "r"(dst), "l"(g_P + src));
            asm volatile("cp.async.commit_group;");
        }
        if (t > 0) {
            // single-thread wait, CLUSTER-scope acquire (sound: pairs with the
            // remote ranks' arrive.release.cluster); bar.sync broadcasts the
            // synchronization to the rest of the CTA.
            if (tid == 0) {
                uint32_t ph = (t - 1) & 1;
                asm volatile(
                    "{\n\t.reg .pred P;\n"
                    "WL_%=:\n\t"
                    "mbarrier.try_wait.parity.acquire.cluster.shared::cta.b64 P, [%0], %1, 0x989680;\n\t"
                    "@!P bra WL_%=;\n\t}"
                    :: "r"(mb_a), "r"(ph) : "memory");
            }
            __syncthreads();            // syncA: h[t-1] visible to all
            // compute: thread (kc,cg) -> 4 gate cols (unit cg) x 4 batches over 32 k
            uint32_t ha = shH_a + ((t - 1) & 1) * 4096 + kc * 512;
            unsigned long long a00 = 0, a01 = 0, a02 = 0, a03 = 0;  // (f,i) x b
            unsigned long long a10 = 0, a11 = 0, a12 = 0, a13 = 0;  // (u,o) x b
#pragma unroll
            for (int kl = 0; kl < 32; kl++) {
                float hx, hy, hz, hw;
                asm volatile("ld.shared.v4.f32 {%0,%1,%2,%3}, [%4];"
                             : "=f"(hx), "=f"(hy), "=f"(hz), "=f"(hw) : "r"(ha));
                unsigned long long h0, h1, h2, h3;
                asm("mov.b64 %0, {%1, %1};" : "=l"(h0) : "f"(hx));
                asm("mov.b64 %0, {%1, %1};" : "=l"(h1) : "f"(hy));
                asm("mov.b64 %0, {%1, %1};" : "=l"(h2) : "f"(hz));
                asm("mov.b64 %0, {%1, %1};" : "=l"(h3) : "f"(hw));
                asm("fma.rn.f32x2 %0, %1, %2, %0;" : "+l"(a00) : "l"(w0[kl]), "l"(h0));
                asm("fma.rn.f32x2 %0, %1, %2, %0;" : "+l"(a01) : "l"(w0[kl]), "l"(h1));
                asm("fma.rn.f32x2 %0, %1, %2, %0;" : "+l"(a02) : "l"(w0[kl]), "l"(h2));
                asm("fma.rn.f32x2 %0, %1, %2, %0;" : "+l"(a03) : "l"(w0[kl]), "l"(h3));
                asm("fma.rn.f32x2 %0, %1, %2, %0;" : "+l"(a10) : "l"(w1[kl]), "l"(h0));
                asm("fma.rn.f32x2 %0, %1, %2, %0;" : "+l"(a11) : "l"(w1[kl]), "l"(h1));
                asm("fma.rn.f32x2 %0, %1, %2, %0;" : "+l"(a12) : "l"(w1[kl]), "l"(h2));
                asm("fma.rn.f32x2 %0, %1, %2, %0;" : "+l"(a13) : "l"(w1[kl]), "l"(h3));
                ha += 16;
            }
            {
                uint32_t r0 = shR_a + (kc * 324 + (cg * 2) * 5) * 8;
                asm volatile("st.shared.b64 [%0], %1;" :: "r"(r0),      "l"(a00));
                asm volatile("st.shared.b64 [%0], %1;" :: "r"(r0 + 8),  "l"(a01));
                asm volatile("st.shared.b64 [%0], %1;" :: "r"(r0 + 16), "l"(a02));
                asm volatile("st.shared.b64 [%0], %1;" :: "r"(r0 + 24), "l"(a03));
                uint32_t r1 = r0 + 40;
                asm volatile("st.shared.b64 [%0], %1;" :: "r"(r1),      "l"(a10));
                asm volatile("st.shared.b64 [%0], %1;" :: "r"(r1 + 8),  "l"(a11));
                asm volatile("st.shared.b64 [%0], %1;" :: "r"(r1 + 16), "l"(a12));
                asm volatile("st.shared.b64 [%0], %1;" :: "r"(r1 + 24), "l"(a13));
            }
        }
        if (tid >= 128) {
            asm volatile("cp.async.wait_group 1;");   // P[t] landed in buf[t&1]
        }
        __syncthreads();                // syncB: shRed + shP ready
        // finalize: thread (jl, bl) owns unit j = jg*32+jl, batch b = ig*4+bl
        float hval = 0.0f;
        if (tid < 128) {
            const float* pp = shP + (t & 1) * 512 + jl * 4 + bl;
            float s0 = pp[0], s1 = pp[128], s2 = pp[256], s3 = pp[384];
            if (t > 0) {
                unsigned long long sfi = 0, suo = 0;
                uint32_t rfi = shR_a + ((jl * 2) * 5 + bl) * 8;
                uint32_t ruo = rfi + 40;
#pragma unroll
                for (int k2 = 0; k2 < 8; k2++) {
                    unsigned long long vfi, vuo;
                    asm volatile("ld.shared.b64 %0, [%1];" : "=l"(vfi) : "r"(rfi));
                    asm volatile("ld.shared.b64 %0, [%1];" : "=l"(vuo) : "r"(ruo));
                    asm("add.rn.f32x2 %0, %0, %1;" : "+l"(sfi) : "l"(vfi));
                    asm("add.rn.f32x2 %0, %0, %1;" : "+l"(suo) : "l"(vuo));
                    rfi += 324 * 8; ruo += 324 * 8;
                }
                float vf, vi, vu, vo;
                asm("mov.b64 {%0, %1}, %2;" : "=f"(vf), "=f"(vi) : "l"(sfi));
                asm("mov.b64 {%0, %1}, %2;" : "=f"(vu), "=f"(vo) : "l"(suo));
                s0 += vf; s1 += vi; s2 += vu; s3 += vo;
            }
            float f  = fast_sig_cos(s0);
            float ii = fast_sig_cos(s1);
            float u  = fast_tanh(__cosf(s2));
            float o  = fast_sig_cos(s3);
            cell = f * cell + ii * u;
            hval = o * fast_tanh(cell);
            g_ysT[(size_t)t * BH + (size_t)(jg * 32 + jl) * 64 + ig * 4 + bl] = hval;
            // publish h[t] to all ranks: packer (bl==0) stores float4 per unit
            float h1 = __shfl_down_sync(0xffffffffu, hval, 1);
            float h2 = __shfl_down_sync(0xffffffffu, hval, 2);
            float h3 = __shfl_down_sync(0xffffffffu, hval, 3);
            if (bl == 0 && t + 1 < Sn) {
                uint32_t loff = (t & 1) * 4096 + (jg * 32 + jl) * 16;
                uint32_t u0 = __float_as_uint(hval), u1 = __float_as_uint(h1);
                uint32_t u2 = __float_as_uint(h2),   u3 = __float_as_uint(h3);
#pragma unroll
                for (int r = 0; r < GJ; r++) {
                    asm volatile("st.shared::cluster.v4.b32 [%0], {%1,%2,%3,%4};"
                                 :: "r"(rbH[r] + loff), "r"(u0), "r"(u1), "r"(u2), "r"(u3));
                }
            }
        }
        __syncthreads();                // syncC: publishes issued by all
        if (tid < GJ && t + 1 < Sn) {
            asm volatile("mbarrier.arrive.release.cluster.shared::cluster.b64 _, [%0];"
                         :: "r"(rb_mb) : "memory");
        }
    }
    if (tid < 128) g_cT[(size_t)(jg * 32 + jl) * 64 + ig * 4 + bl] = cell;
}

// ---------------- phase 3a: qfeat = cos(ysT + phi), transpose to [B][S][H] ----------------
__global__ void __launch_bounds__(256) qfeat_kernel(const float* __restrict__ phi,
                                                    float* __restrict__ out) {
    __shared__ float smq[64 * 129];
    int s = blockIdx.x, half = blockIdx.y;
    int h0 = half * 128;
    int tid = threadIdx.x;
    const float* src = g_ysT + (size_t)s * BH + (size_t)h0 * 64;
#pragma unroll
    for (int r = 0; r < 32; r++) {
        int i = tid + r * 256;
        int h = i >> 6, b = i & 63;
        smq[b * 129 + h] = __cosf(src[i] + phi[h0 + h]);
    }
    __syncthreads();
#pragma unroll
    for (int r = 0; r < 32; r++) {
        int i = tid + r * 256;
        int b = i >> 7, h = i & 127;
        out[(size_t)b * (Sn * Hn) + (size_t)s * Hn + h0 + h] = smq[b * 129 + h];
    }
}

// ---------------- phase 3b: attention context + residual add ----------------
__global__ void __launch_bounds__(128) attn_kernel(const float* __restrict__ tha,
                                                   float* __restrict__ out) {
    int b = blockIdx.x;
    int h = blockIdx.y * 128 + threadIdx.x;
    float th = tha[h];
    float se = 0.0f, sq = 0.0f;
    size_t base = (size_t)b * Sn * Hn + h;
#pragma unroll 4
    for (int s = 0; s < Sn; s++) {
        float q = out[base + (size_t)s * Hn];
        float e = __expf(fast_tanh(__cosf(q + th)));
        se += e; sq += e * q;
    }
    float ctx = sq / se;
#pragma unroll 4
    for (int s = 0; s < Sn; s++) {
        out[base + (size_t)s * Hn] += ctx;
    }
}

// ---------------- phase 3c: hx, cx tail ----------------
__global__ void tail_kernel(float* __restrict__ out) {
    int i = blockIdx.x * blockDim.x + threadIdx.x;
    if (i < BH) {
        int b = i >> 8, jx = i & 255;
        out[(size_t)Bn * Sn * Hn + i]      = g_ysT[(size_t)(Sn - 1) * BH + jx * 64 + b];
        out[(size_t)Bn * Sn * Hn + BH + i] = g_cT[jx * 64 + b];
    }
}

// ---------------- launch ----------------
extern "C" void kernel_launch(void* const* d_in, const int* in_sizes, int n_in,
                              void* d_out, int out_size) {
    const float* X   = (const float*)d_in[0];
    const float* Wf  = (const float*)d_in[1];
    const float* bf  = (const float*)d_in[2];
    const float* Wi  = (const float*)d_in[3];
    const float* bi  = (const float*)d_in[4];
    const float* Wu  = (const float*)d_in[5];
    const float* bu  = (const float*)d_in[6];
    const float* Wo  = (const float*)d_in[7];
    const float* bo  = (const float*)d_in[8];
    const float* thf = (const float*)d_in[9];
    const float* thi = (const float*)d_in[10];
    const float* thu = (const float*)d_in[11];
    const float* tho = (const float*)d_in[12];
    const float* phi = (const float*)d_in[13];
    const float* tha = (const float*)d_in[14];
    float* out = (float*)d_out;

    cudaFuncSetAttribute(lstm_main_kernel,
                         cudaFuncAttributeMaxDynamicSharedMemorySize, SMEM_MAIN_BYTES);

    prep_kernel<<<1024, 256>>>(Wf, bf, Wi, bi, Wu, bu, Wo, bo, thf, thi, thu, tho);
    xproj_kernel<<<dim3(8, 512), 256>>>(X);
    lstm_main_kernel<<<NBLK, 256, SMEM_MAIN_BYTES>>>();
    qfeat_kernel<<<dim3(Sn, 2), 256>>>(phi, out);
    attn_kernel<<<dim3(Bn, 2), 128>>>(tha, out);
    if (out_size >= Bn * Sn * Hn + 2 * BH) {
        tail_kernel<<<64, 256>>>(out);
    }
}